// round 4
// baseline (speedup 1.0000x reference)
#include <cuda_runtime.h>
#include <math.h>

#define NN 100000
#define EE 1600000
#define KK 10
#define HID 64
#define FIN 256

// ---------------- scratch (no allocations allowed) ----------------
__device__ __align__(16) float g_T0[NN * HID];
__device__ __align__(16) float g_T1[NN * HID];
__device__ __align__(16) float g_T2[NN * HID];
__device__ int   g_cnt_row[NN];
__device__ int   g_cnt_col[NN];
__device__ int   g_rowptr[NN + 1];
__device__ int   g_cur[NN];
__device__ float g_dis[NN];
__device__ int   g_rows32[EE];
__device__ int   g_cols32[EE];
__device__ int   g_esrc[EE];
__device__ __align__(16) float g_ew[EE];
__device__ float g_coe[16];
__device__ int   g_tmpinc[NN];
__device__ int   g_bsum[128];
__device__ int   g_boff[128];
__device__ int   g_is64;

// ---------------- dtype detect: int64 edge_index has zero high words ----------------
__global__ void detect_kernel(const unsigned int* __restrict__ ei32) {
    if (threadIdx.x != 0 || blockIdx.x != 0) return;
    int zeros = 0;
    for (int i = 0; i < 8; i++)
        if (ei32[2 * i + 1] == 0u) zeros++;
    g_is64 = (zeros == 8) ? 1 : 0;
}

// ---------------- histogram + convert indices to int32 ----------------
__global__ void hist_kernel(const void* __restrict__ eiv) {
    int e = blockIdx.x * blockDim.x + threadIdx.x;
    if (e >= EE) return;
    int r, c;
    if (g_is64) {
        const long long* ei = (const long long*)eiv;
        r = (int)ei[e];
        c = (int)ei[EE + e];
    } else {
        const int* ei = (const int*)eiv;
        r = ei[e];
        c = ei[EE + e];
    }
    if ((unsigned)r >= NN || (unsigned)c >= NN) { r = 0; c = 0; }
    g_rows32[e] = r;
    g_cols32[e] = c;
    atomicAdd(&g_cnt_row[r], 1);
    atomicAdd(&g_cnt_col[c], 1);
}

// ---------------- dis = deg>0 ? rsqrt(deg) : 0 ----------------
__global__ void dis_kernel() {
    int i = blockIdx.x * blockDim.x + threadIdx.x;
    if (i >= NN) return;
    int d = g_cnt_row[i];
    g_dis[i] = (d > 0) ? rsqrtf((float)d) : 0.0f;
}

// ---------------- 3-phase exclusive scan of cnt_col -> rowptr ----------------
__global__ void scan1_kernel() {
    __shared__ int s[1024];
    int tid = threadIdx.x;
    int i = blockIdx.x * 1024 + tid;
    int v = (i < NN) ? g_cnt_col[i] : 0;
    s[tid] = v;
    __syncthreads();
    for (int off = 1; off < 1024; off <<= 1) {
        int t = 0;
        if (tid >= off) t = s[tid - off];
        __syncthreads();
        s[tid] += t;
        __syncthreads();
    }
    if (i < NN) g_tmpinc[i] = s[tid];
    if (tid == 1023) g_bsum[blockIdx.x] = s[1023];
}

__global__ void scan2_kernel(int nb) {
    if (blockIdx.x == 0 && threadIdx.x == 0) {
        int run = 0;
        for (int b = 0; b < nb; b++) {
            g_boff[b] = run;
            run += g_bsum[b];
        }
    }
}

__global__ void scan3_kernel() {
    int i = blockIdx.x * blockDim.x + threadIdx.x;
    if (i == 0) g_rowptr[0] = 0;
    if (i < NN) g_rowptr[i + 1] = g_tmpinc[i] + g_boff[i >> 10];
}

// ---------------- scatter edges into CSR-by-dst, fused edge weight ----------------
__global__ void scatter_kernel() {
    int e = blockIdx.x * blockDim.x + threadIdx.x;
    if (e >= EE) return;
    int r = g_rows32[e];
    int c = g_cols32[e];
    int p = atomicAdd(&g_cur[c], 1);
    g_esrc[p] = r;
    g_ew[p] = -(g_dis[r] * g_dis[c]);
}

// ---------------- Chebyshev coefficients from temp ----------------
__global__ void coe_kernel(const float* __restrict__ temp) {
    if (blockIdx.x != 0 || threadIdx.x != 0) return;
    double xs[KK + 1];
    float m0[KK + 1], m1[KK + 1], tv[KK + 1];
    for (int j = 0; j <= KK; j++) {
        xs[j] = cos((KK - j + 0.5) * M_PI / (KK + 1));
        tv[j] = temp[j];
    }
    const float f = 2.0f / (KK + 1);
    float s0 = 0.f, s1 = 0.f;
    for (int j = 0; j <= KK; j++) {
        m0[j] = 1.0f;
        m1[j] = (float)xs[j];
        s0 += tv[j] * m0[j];
        s1 += tv[j] * m1[j];
    }
    g_coe[0] = f * s0;
    g_coe[1] = f * s1;
    for (int i = 2; i <= KK; i++) {
        float s = 0.f;
        for (int j = 0; j <= KK; j++) {
            float m2 = (float)(2.0 * xs[j] * (double)m1[j] - (double)m0[j]);
            s += tv[j] * m2;
            m0[j] = m1[j];
            m1[j] = m2;
        }
        g_coe[i] = f * s;
    }
}

// ---------------- fused MLP: h = relu(x@W1+b1)@W2+b2 ----------------
// 64-row tile per block, 256 threads, 4x4 register micro-tiles.
__global__ __launch_bounds__(256) void mlp_kernel(
    const float* __restrict__ x, const float* __restrict__ W1,
    const float* __restrict__ b1, const float* __restrict__ W2,
    const float* __restrict__ b2, float* __restrict__ h)
{
    __shared__ __align__(16) float sbuf[64 * 33 + 32 * 64];  // 4160 floats
    __shared__ __align__(16) float Hs[64 * 65];
    float* Xs = sbuf;
    float* Ws = sbuf + 64 * 33;

    int tid = threadIdx.x;
    int tx = tid & 15;
    int ty = tid >> 4;
    int row0 = blockIdx.x * 64;

    float acc[4][4];
#pragma unroll
    for (int i = 0; i < 4; i++)
#pragma unroll
        for (int j = 0; j < 4; j++) acc[i][j] = 0.f;

    for (int kc = 0; kc < FIN; kc += 32) {
        for (int i = tid; i < 64 * 32; i += 256) {
            int r = i >> 5, k = i & 31;
            int gr = row0 + r;
            Xs[r * 33 + k] = (gr < NN) ? x[gr * FIN + kc + k] : 0.f;
        }
        for (int i = tid; i < 32 * 64; i += 256) {
            int k = i >> 6, j = i & 63;
            Ws[i] = W1[(kc + k) * HID + j];
        }
        __syncthreads();
#pragma unroll
        for (int k = 0; k < 32; k++) {
            float a0 = Xs[(ty * 4 + 0) * 33 + k];
            float a1 = Xs[(ty * 4 + 1) * 33 + k];
            float a2 = Xs[(ty * 4 + 2) * 33 + k];
            float a3 = Xs[(ty * 4 + 3) * 33 + k];
            float4 b = *(const float4*)&Ws[k * 64 + tx * 4];
            acc[0][0] += a0 * b.x; acc[0][1] += a0 * b.y; acc[0][2] += a0 * b.z; acc[0][3] += a0 * b.w;
            acc[1][0] += a1 * b.x; acc[1][1] += a1 * b.y; acc[1][2] += a1 * b.z; acc[1][3] += a1 * b.w;
            acc[2][0] += a2 * b.x; acc[2][1] += a2 * b.y; acc[2][2] += a2 * b.z; acc[2][3] += a2 * b.w;
            acc[3][0] += a3 * b.x; acc[3][1] += a3 * b.y; acc[3][2] += a3 * b.z; acc[3][3] += a3 * b.w;
        }
        __syncthreads();
    }

    float4 bb = *(const float4*)&b1[tx * 4];
#pragma unroll
    for (int i = 0; i < 4; i++) {
        int r = ty * 4 + i;
        Hs[r * 65 + tx * 4 + 0] = fmaxf(acc[i][0] + bb.x, 0.f);
        Hs[r * 65 + tx * 4 + 1] = fmaxf(acc[i][1] + bb.y, 0.f);
        Hs[r * 65 + tx * 4 + 2] = fmaxf(acc[i][2] + bb.z, 0.f);
        Hs[r * 65 + tx * 4 + 3] = fmaxf(acc[i][3] + bb.w, 0.f);
    }
    for (int i = tid; i < 64 * 64; i += 256) sbuf[i] = W2[i];
    __syncthreads();

    float acc2[4][4];
#pragma unroll
    for (int i = 0; i < 4; i++)
#pragma unroll
        for (int j = 0; j < 4; j++) acc2[i][j] = 0.f;

#pragma unroll
    for (int k = 0; k < 64; k++) {
        float a0 = Hs[(ty * 4 + 0) * 65 + k];
        float a1 = Hs[(ty * 4 + 1) * 65 + k];
        float a2 = Hs[(ty * 4 + 2) * 65 + k];
        float a3 = Hs[(ty * 4 + 3) * 65 + k];
        float4 b = *(const float4*)&sbuf[k * 64 + tx * 4];
        acc2[0][0] += a0 * b.x; acc2[0][1] += a0 * b.y; acc2[0][2] += a0 * b.z; acc2[0][3] += a0 * b.w;
        acc2[1][0] += a1 * b.x; acc2[1][1] += a1 * b.y; acc2[1][2] += a1 * b.z; acc2[1][3] += a1 * b.w;
        acc2[2][0] += a2 * b.x; acc2[2][1] += a2 * b.y; acc2[2][2] += a2 * b.z; acc2[2][3] += a2 * b.w;
        acc2[3][0] += a3 * b.x; acc2[3][1] += a3 * b.y; acc2[3][2] += a3 * b.z; acc2[3][3] += a3 * b.w;
    }

    float4 c2 = *(const float4*)&b2[tx * 4];
#pragma unroll
    for (int i = 0; i < 4; i++) {
        int gr = row0 + ty * 4 + i;
        if (gr < NN) {
            float4 o;
            o.x = acc2[i][0] + c2.x;
            o.y = acc2[i][1] + c2.y;
            o.z = acc2[i][2] + c2.z;
            o.w = acc2[i][3] + c2.w;
            *(float4*)&h[gr * HID + tx * 4] = o;
        }
    }
}

// ---------------- fused Chebyshev propagation ----------------
// warp per node, zero atomics (CSR gather). Fuses:
//   first=1: Tnew = prop(v);            out = coe[0]/2 * v + coe[1]*Tnew   (v == tpp == h)
//   first=0: Tnew = 2*prop(v) - tpp;    out += coe[ci]*Tnew
__global__ __launch_bounds__(256) void prop_kernel(
    const float* __restrict__ v, const float* __restrict__ tpp,
    float* __restrict__ tnew, float* __restrict__ outv,
    int ci, int first)
{
    int node = blockIdx.x * 8 + (threadIdx.x >> 5);
    int lane = threadIdx.x & 31;
    if (node >= NN) return;

    int beg = g_rowptr[node];
    int end = g_rowptr[node + 1];

    float2 acc = make_float2(0.f, 0.f);
    const float2* __restrict__ v2 = (const float2*)v;

    for (int p = beg; p < end; p += 32) {
        int cnt = min(32, end - p);
        // pack (src, weight) into one 64-bit shuffle payload
        long long packed = 0;
        if (lane < cnt) {
            int s = __ldg(&g_esrc[p + lane]);
            float w = __ldg(&g_ew[p + lane]);
            packed = ((long long)__float_as_int(w) << 32) | (unsigned int)s;
        }
        for (int j = 0; j < cnt; j++) {
            long long pj = __shfl_sync(0xffffffffu, packed, j);
            int s = (int)(unsigned int)pj;
            float ww = __int_as_float((int)(pj >> 32));
            float2 val = v2[s * 32 + lane];
            acc.x += ww * val.x;
            acc.y += ww * val.y;
        }
    }

    int idx = node * 32 + lane;
    float cnew = g_coe[ci];
    float2 t;
    if (first) {
        t = acc;
    } else {
        float2 pv = ((const float2*)tpp)[idx];
        t.x = 2.f * acc.x - pv.x;
        t.y = 2.f * acc.y - pv.y;
    }
    ((float2*)tnew)[idx] = t;

    float2 o;
    if (first) {
        float c0h = 0.5f * g_coe[0];
        float2 hv = ((const float2*)tpp)[idx];
        o.x = c0h * hv.x + cnew * t.x;
        o.y = c0h * hv.y + cnew * t.y;
    } else {
        o = ((float2*)outv)[idx];
        o.x += cnew * t.x;
        o.y += cnew * t.y;
    }
    ((float2*)outv)[idx] = o;
}

// ---------------- launch ----------------
extern "C" void kernel_launch(void* const* d_in, const int* in_sizes, int n_in,
                              void* d_out, int out_size) {
    const float* x    = (const float*)d_in[0];
    const void*  ei   = d_in[1];
    const float* W1   = (const float*)d_in[2];
    const float* b1   = (const float*)d_in[3];
    const float* W2   = (const float*)d_in[4];
    const float* b2   = (const float*)d_in[5];
    const float* temp = (const float*)d_in[6];
    float*       out  = (float*)d_out;

    void *pT0, *pT1, *pT2, *pCntR, *pCntC, *pRowptr, *pCur;
    cudaGetSymbolAddress(&pT0, g_T0);
    cudaGetSymbolAddress(&pT1, g_T1);
    cudaGetSymbolAddress(&pT2, g_T2);
    cudaGetSymbolAddress(&pCntR, g_cnt_row);
    cudaGetSymbolAddress(&pCntC, g_cnt_col);
    cudaGetSymbolAddress(&pRowptr, g_rowptr);
    cudaGetSymbolAddress(&pCur, g_cur);

    // --- graph preprocessing: degrees, dis, CSR-by-dst, edge weights ---
    cudaMemsetAsync(pCntR, 0, NN * sizeof(int), 0);
    cudaMemsetAsync(pCntC, 0, NN * sizeof(int), 0);
    detect_kernel<<<1, 32>>>((const unsigned int*)ei);
    hist_kernel<<<(EE + 255) / 256, 256>>>(ei);
    dis_kernel<<<(NN + 255) / 256, 256>>>();
    int nb = (NN + 1023) / 1024;
    scan1_kernel<<<nb, 1024>>>();
    scan2_kernel<<<1, 1>>>(nb);
    scan3_kernel<<<(NN + 255) / 256, 256>>>();
    cudaMemcpyAsync(pCur, pRowptr, NN * sizeof(int), cudaMemcpyDeviceToDevice, 0);
    scatter_kernel<<<(EE + 255) / 256, 256>>>();

    // --- coefficients ---
    coe_kernel<<<1, 32>>>(temp);

    // --- MLP -> T0 (= h = Tx_0) ---
    mlp_kernel<<<(NN + 63) / 64, 256>>>(x, W1, b1, W2, b2, (float*)pT0);

    // --- Chebyshev recurrence, fully fused ---
    prop_kernel<<<NN / 8, 256>>>((const float*)pT0, (const float*)pT0,
                                 (float*)pT1, out, 1, 1);
    float* t0 = (float*)pT0;
    float* t1 = (float*)pT1;
    float* t2 = (float*)pT2;
    for (int i = 2; i <= KK; i++) {
        prop_kernel<<<NN / 8, 256>>>(t1, t0, t2, out, i, 0);
        float* tmp = t0; t0 = t1; t1 = t2; t2 = tmp;
    }
}